// round 4
// baseline (speedup 1.0000x reference)
#include <cuda_runtime.h>
#include <cstdint>
#include <cstddef>

// ---------------- Problem constants ----------------
#define BB 64
#define SS 2048
#define DD 6
#define HH 8
#define NCHAIN (BB*HH)      // 512 independent scan chains
#define CS 16               // steps per chunk
#define NC (SS/CS)          // 128 chunks per chain
#define NROW (BB*SS)        // 131072 output rows
#define EPSN 1e-8f

// ---------------- Cl(4,1) sign (compile-time foldable) ----------------
__host__ __device__ constexpr int cpopc(unsigned v){ int c=0; while(v){ c += (int)(v&1u); v>>=1; } return c; }
__host__ __device__ constexpr float csign(int a, int b){
    int s = 0;
    int aa = a >> 1;
    while (aa){ s += cpopc((unsigned)(aa & b)); aa >>= 1; }
    if ((a & b) & 16) s++;              // e5*e5 = -1 (metric +,+,+,+,-)
    return (s & 1) ? -1.0f : 1.0f;
}

// ---------------- Scratch (device globals; no allocation) ----------------
// d_T[bh][comp][s_local][c]   : addr = ((bh*32 + k)*CS + s)*NC + c
__device__ static float d_T[(size_t)NCHAIN * 32 * CS * NC];
// g_T[chain][c][comp]         : addr = (chain*NC + c)*32 + k
__device__ static float g_T[(size_t)NCHAIN * NC * 32];
// g_E[chain][comp][c]         : addr = (chain*32 + k)*NC + c
__device__ static float g_E[(size_t)NCHAIN * 32 * NC];
// psi_T[j][b][s_local][c]     : addr = j*NROW + b*SS + s*NC + c   (j = h*32+k)
__device__ static float psi_T[(size_t)256 * NROW];

// ======================================================================
// Kernel 0: delta. block = (b, s_local); thread = c; loops over 8 heads.
// delta(bh, s=c*16+s_l)[k] -> d_T[((bh*32+k)*16+s_l)*128 + c]  (lane-coalesced)
// ======================================================================
__global__ void __launch_bounds__(128) k_delta(const float* __restrict__ x,
                                               const float* __restrict__ W_in,
                                               const float* __restrict__ b_in)
{
    __shared__ float Wsm[DD * 256];
    __shared__ float bsm[256];

    const int tid = threadIdx.x;
    const int b   = blockIdx.x >> 4;
    const int s_l = blockIdx.x & 15;
    const int c   = tid;
    const int s   = c * CS + s_l;

    // stage weights
    for (int i = tid; i < DD * 256 / 4; i += 128)
        reinterpret_cast<float4*>(Wsm)[i] = __ldg(reinterpret_cast<const float4*>(W_in) + i);
    for (int i = tid; i < 64; i += 128)
        reinterpret_cast<float4*>(bsm)[i] = __ldg(reinterpret_cast<const float4*>(b_in) + i);
    __syncthreads();

    // x[b][s][0..5]
    const float* xp = x + ((size_t)b * SS + s) * DD;
    float xv[DD];
    {
        float2 v0 = __ldg(reinterpret_cast<const float2*>(xp));
        float2 v1 = __ldg(reinterpret_cast<const float2*>(xp) + 1);
        float2 v2 = __ldg(reinterpret_cast<const float2*>(xp) + 2);
        xv[0]=v0.x; xv[1]=v0.y; xv[2]=v1.x; xv[3]=v1.y; xv[4]=v2.x; xv[5]=v2.y;
    }

#pragma unroll
    for (int h = 0; h < HH; h++){
        float u[32];
#pragma unroll
        for (int k4 = 0; k4 < 8; k4++){
            float4 bv = *reinterpret_cast<const float4*>(&bsm[h*32 + k4*4]);
            u[k4*4+0]=bv.x; u[k4*4+1]=bv.y; u[k4*4+2]=bv.z; u[k4*4+3]=bv.w;
        }
#pragma unroll
        for (int d = 0; d < DD; d++){
            const float xd = xv[d];
#pragma unroll
            for (int k4 = 0; k4 < 8; k4++){
                float4 w = *reinterpret_cast<const float4*>(&Wsm[d*256 + h*32 + k4*4]);
                u[k4*4+0] = fmaf(xd, w.x, u[k4*4+0]);
                u[k4*4+1] = fmaf(xd, w.y, u[k4*4+1]);
                u[k4*4+2] = fmaf(xd, w.z, u[k4*4+2]);
                u[k4*4+3] = fmaf(xd, w.w, u[k4*4+3]);
            }
        }
        u[0] += 1.0f;

        float n = 0.f;
#pragma unroll
        for (int k = 0; k < 32; k++) n = fmaf(u[k], u[k], n);
        const float inv = 1.0f / (sqrtf(n) + EPSN);

        const int bh = b * HH + h;
        float* dst = d_T + ((size_t)bh*32*CS + s_l) * NC + c;   // + k*CS*NC
#pragma unroll
        for (int k = 0; k < 32; k++)
            dst[(size_t)k * CS * NC] = u[k] * inv;
    }
}

// ---------------- raw geometric product (no normalize), coalesced d loads ----
// dstep points at d_T[bh][0][s][0] + c ; comp i at offset i*CS*NC
__device__ __forceinline__ void gp_raw(const float* __restrict__ dstep, const float P[32], float Q[32])
{
#pragma unroll
    for (int k = 0; k < 32; k++) Q[k] = 0.0f;
#pragma unroll
    for (int i = 0; i < 32; i++){
        const float di = __ldg(dstep + (size_t)i * CS * NC);
#pragma unroll
        for (int k = 0; k < 32; k++){
            Q[k] = fmaf((csign(i, i ^ k) > 0.0f) ? di : -di, P[i ^ k], Q[k]);
        }
    }
}

// ======================================================================
// Kernel 1: chunk totals. block = bh; thread = c. 15 raw GPs + final normalize.
// ======================================================================
__global__ void __launch_bounds__(128) k_chunk()
{
    const int bh = blockIdx.x;
    const int c  = threadIdx.x;
    const float* base = d_T + (size_t)bh * 32 * CS * NC + c;   // + k*CS*NC + s*NC

    float P[32], Q[32];
    // step 0: P = d_0  (N(d o identity) = d)
#pragma unroll
    for (int k = 0; k < 32; k++) P[k] = __ldg(base + (size_t)k * CS * NC);

    for (int s = 1; s < CS; s++){
        gp_raw(base + (size_t)s * NC, P, Q);
#pragma unroll
        for (int k = 0; k < 32; k++) P[k] = Q[k];
    }

    float n = 0.f;
#pragma unroll
    for (int k = 0; k < 32; k++) n = fmaf(P[k], P[k], n);
    const float inv = 1.0f / (sqrtf(n) + EPSN);

    float4* tp = reinterpret_cast<float4*>(g_T + ((size_t)bh * NC + c) * 32);
#pragma unroll
    for (int q = 0; q < 8; q++)
        tp[q] = make_float4(P[4*q]*inv, P[4*q+1]*inv, P[4*q+2]*inv, P[4*q+3]*inv);
}

// ======================================================================
// Kernel 2: sequential exclusive scan of chunk totals (warp per chain)
// ======================================================================
__global__ void k_scan()
{
    const int lane  = threadIdx.x & 31;
    const int chain = blockIdx.x * (blockDim.x >> 5) + (threadIdx.x >> 5);

    float sg[32];
#pragma unroll
    for (int i = 0; i < 32; i++) sg[i] = csign(i, i ^ lane);

    float Ev = (lane == 0) ? 1.0f : 0.0f;
    g_E[((size_t)chain*32 + lane) * NC + 0] = Ev;

    for (int c = 0; c < NC - 1; c++){
        const float Tv = g_T[((size_t)chain * NC + c) * 32 + lane];   // coalesced
        float acc = 0.0f;
#pragma unroll
        for (int i = 0; i < 32; i++){
            const float Ti = __shfl_sync(0xffffffffu, Tv, i);
            const float Pi = __shfl_xor_sync(0xffffffffu, Ev, i);
            acc = fmaf(sg[i] * Ti, Pi, acc);
        }
        float ss = acc * acc;
#pragma unroll
        for (int off = 16; off; off >>= 1) ss += __shfl_xor_sync(0xffffffffu, ss, off);
        Ev = acc / (sqrtf(ss) + EPSN);
        g_E[((size_t)chain*32 + lane) * NC + c + 1] = Ev;
    }
}

// ======================================================================
// Kernel 3: expand. block = bh; thread = c. Carry unnormalized; store N(Q).
// ======================================================================
__global__ void __launch_bounds__(128) k_expand()
{
    const int bh = blockIdx.x;
    const int c  = threadIdx.x;
    const int b  = bh >> 3;
    const int h  = bh & 7;

    const float* base = d_T + (size_t)bh * 32 * CS * NC + c;

    float P[32], Q[32];
#pragma unroll
    for (int k = 0; k < 32; k++)
        P[k] = __ldg(g_E + ((size_t)bh*32 + k) * NC + c);

    float* psb = psi_T + (size_t)h*32*NROW + (size_t)b * SS + c;   // + k*NROW + s*NC

    for (int s = 0; s < CS; s++){
        gp_raw(base + (size_t)s * NC, P, Q);

        float n = 0.f;
#pragma unroll
        for (int k = 0; k < 32; k++) n = fmaf(Q[k], Q[k], n);
        const float inv = 1.0f / (sqrtf(n) + EPSN);

        float* op = psb + (size_t)s * NC;
#pragma unroll
        for (int k = 0; k < 32; k++)
            op[(size_t)k * NROW] = Q[k] * inv;                      // lane-coalesced

#pragma unroll
        for (int k = 0; k < 32; k++) P[k] = Q[k];                   // carry raw
    }
}

// ======================================================================
// Kernel 4: projection. warp handles 32 rows r (lane = c run); coalesced
// column loads from psi_T; out store scattered (cheap).
// ======================================================================
__global__ void __launch_bounds__(256) k_proj(const float* __restrict__ W_out,
                                              const float* __restrict__ b_out,
                                              float* __restrict__ out)
{
    __shared__ float Wsm[256 * 32];
    __shared__ float bsm[32];

    const int tid = threadIdx.x;
    for (int i = tid; i < 256 * 32 / 4; i += 256)
        reinterpret_cast<float4*>(Wsm)[i] = __ldg(reinterpret_cast<const float4*>(W_out) + i);
    if (tid < 8)
        reinterpret_cast<float4*>(bsm)[tid] = __ldg(reinterpret_cast<const float4*>(b_out) + tid);
    __syncthreads();

    const int lane = tid & 31;
    const int gw   = blockIdx.x * 8 + (tid >> 5);
    const size_t r = (size_t)gw * 32 + lane;

    const float* ap = psi_T + r;

    float acc[32];
#pragma unroll
    for (int j = 0; j < 32; j++) acc[j] = 0.f;

#pragma unroll 8
    for (int j = 0; j < 256; j++){
        const float a = __ldg(ap + (size_t)j * NROW);               // coalesced
#pragma unroll
        for (int q = 0; q < 8; q++){
            const float4 w = *reinterpret_cast<const float4*>(&Wsm[j*32 + q*4]);
            acc[q*4+0] = fmaf(a, w.x, acc[q*4+0]);
            acc[q*4+1] = fmaf(a, w.y, acc[q*4+1]);
            acc[q*4+2] = fmaf(a, w.z, acc[q*4+2]);
            acc[q*4+3] = fmaf(a, w.w, acc[q*4+3]);
        }
    }

#pragma unroll
    for (int j = 0; j < 32; j++) acc[j] += bsm[j];

    float n = 0.f;
#pragma unroll
    for (int j = 0; j < 32; j++) n = fmaf(acc[j], acc[j], n);
    const float inv = 1.0f / (sqrtf(n) + EPSN);

    // r = b*2048 + s_l*128 + c ; true time index t = c*16 + s_l
    const int b   = (int)(r >> 11);
    const int rem = (int)(r & 2047);
    const int s_l = rem >> 7;
    const int c   = rem & 127;
    const int t   = c * CS + s_l;

    float4* op = reinterpret_cast<float4*>(out + ((size_t)b * SS + t) * 32);
#pragma unroll
    for (int q = 0; q < 8; q++)
        op[q] = make_float4(acc[4*q]*inv, acc[4*q+1]*inv, acc[4*q+2]*inv, acc[4*q+3]*inv);
}

// ======================================================================
extern "C" void kernel_launch(void* const* d_in, const int* in_sizes, int n_in,
                              void* d_out, int out_size)
{
    const float* x     = (const float*)d_in[0];
    const float* W_in  = (const float*)d_in[1];
    const float* b_in  = (const float*)d_in[2];
    const float* W_out = (const float*)d_in[3];
    const float* b_out = (const float*)d_in[4];
    float* out = (float*)d_out;

    k_delta<<<BB * CS, 128>>>(x, W_in, b_in);     // 1024 blocks
    k_chunk<<<NCHAIN, 128>>>();                   // 512 blocks
    k_scan<<<NCHAIN / 8, 256>>>();                // 64 blocks
    k_expand<<<NCHAIN, 128>>>();                  // 512 blocks
    k_proj<<<NROW / (32 * 8), 256>>>(W_out, b_out, out);  // 512 blocks
}

// round 5
// speedup vs baseline: 1.1064x; 1.1064x over previous
#include <cuda_runtime.h>
#include <cstdint>
#include <cstddef>

// ---------------- Problem constants ----------------
#define BB 64
#define SS 2048
#define DD 6
#define HH 8
#define NCHAIN (BB*HH)      // 512 independent scan chains
#define CS 8                // steps per chunk
#define NC (SS/CS)          // 256 chunks per chain
#define SEG 64              // chunks per scan segment
#define NSEG (NC/SEG)       // 4 segments per chain
#define NROW (BB*SS)        // 131072 output rows
#define EPSN 1e-8f

// ---------------- Cl(4,1) sign (compile-time foldable) ----------------
__host__ __device__ constexpr int cpopc(unsigned v){ int c=0; while(v){ c += (int)(v&1u); v>>=1; } return c; }
__host__ __device__ constexpr float csign(int a, int b){
    int s = 0;
    int aa = a >> 1;
    while (aa){ s += cpopc((unsigned)(aa & b)); aa >>= 1; }
    if ((a & b) & 16) s++;              // e5*e5 = -1 (metric +,+,+,+,-)
    return (s & 1) ? -1.0f : 1.0f;
}

// ---------------- Scratch (device globals; no allocation) ----------------
__device__ static float g_d [(size_t)NCHAIN * SS * 32];     // normalized deltas, AoS
__device__ static float g_L [(size_t)NCHAIN * SS * 32];     // local prefix products (raw), AoS
__device__ static float g_T [(size_t)NCHAIN * NC * 32];     // chunk totals (normalized), AoS
__device__ static float g_El[(size_t)NCHAIN * NC * 32];     // segment-local exclusive prefixes
__device__ static float g_St[(size_t)NCHAIN * NSEG * 32];   // segment totals
__device__ static float g_G [(size_t)NCHAIN * NSEG * 32];   // segment exclusive prefixes
__device__ static float g_E [(size_t)NCHAIN * NC * 32];     // final per-chunk seeds (normalized)
__device__ static float psi_T[(size_t)256 * NROW];          // psi transposed: [j][b*SS+t]

// ======================================================================
// Kernel 0: delta. warp per (b, s); loops over 8 heads; lane = component k.
// ======================================================================
__global__ void k_delta(const float* __restrict__ x,
                        const float* __restrict__ W_in,
                        const float* __restrict__ b_in)
{
    const int lane = threadIdx.x & 31;
    const int gw = blockIdx.x * (blockDim.x >> 5) + (threadIdx.x >> 5);  // [0, B*S)
    const int s  = gw & (SS - 1);
    const int b  = gw >> 11;

    const float* xp = x + ((size_t)b * SS + s) * DD;
    float xv[DD];
#pragma unroll
    for (int d = 0; d < DD; d++) xv[d] = __ldg(xp + d);

#pragma unroll
    for (int h = 0; h < HH; h++){
        float u = __ldg(b_in + h*32 + lane);
#pragma unroll
        for (int d = 0; d < DD; d++)
            u = fmaf(xv[d], __ldg(W_in + d*(HH*32) + h*32 + lane), u);
        if (lane == 0) u += 1.0f;

        float ss = u * u;
#pragma unroll
        for (int off = 16; off; off >>= 1) ss += __shfl_xor_sync(0xffffffffu, ss, off);
        const float inv = 1.0f / (sqrtf(ss) + EPSN);

        g_d[(((size_t)(b*HH + h)) * SS + s) * 32 + lane] = u * inv;
    }
}

// ---------------- raw GP with float4-streamed left operand ----------------
// Q = d (at dp) o P      (d = left/new, P = right/old)
__device__ __forceinline__ void gp_f4(const float4* __restrict__ dp, const float P[32], float Q[32])
{
#pragma unroll
    for (int k = 0; k < 32; k++) Q[k] = 0.0f;
#pragma unroll
    for (int q = 0; q < 8; q++){
        const float4 v = __ldg(dp + q);
#pragma unroll
        for (int t = 0; t < 4; t++){
            const int i = 4*q + t;
            const float dv = (t == 0) ? v.x : (t == 1) ? v.y : (t == 2) ? v.z : v.w;
#pragma unroll
            for (int k = 0; k < 32; k++)
                Q[k] = fmaf((csign(i, i ^ k) > 0.0f) ? dv : -dv, P[i ^ k], Q[k]);
        }
    }
}

// ======================================================================
// Kernel 1: chunk local prefixes. thread per (bh, c): 7 serial GPs.
// Stores raw L for every step; normalized total -> g_T.
// ======================================================================
__global__ void __launch_bounds__(128) k_chunkL()
{
    const int idx = blockIdx.x * blockDim.x + threadIdx.x;   // [0, NCHAIN*NC)
    const int c  = idx & (NC - 1);
    const int bh = idx >> 8;                                 // NC = 256

    const float4* dp = reinterpret_cast<const float4*>(g_d + ((size_t)bh * SS + c * CS) * 32);
    float4*       lp = reinterpret_cast<float4*>(g_L + ((size_t)bh * SS + c * CS) * 32);

    float P[32], Q[32];
    // step 0: L_0 = d_0  (N(d o identity) = d up to scale)
#pragma unroll
    for (int q = 0; q < 8; q++){
        const float4 v = __ldg(dp + q);
        P[4*q]=v.x; P[4*q+1]=v.y; P[4*q+2]=v.z; P[4*q+3]=v.w;
        lp[q] = v;
    }

    for (int s = 1; s < CS; s++){
        gp_f4(dp + s*8, P, Q);
#pragma unroll
        for (int q = 0; q < 8; q++)
            lp[s*8 + q] = make_float4(Q[4*q], Q[4*q+1], Q[4*q+2], Q[4*q+3]);
#pragma unroll
        for (int k = 0; k < 32; k++) P[k] = Q[k];
    }

    float n = 0.f;
#pragma unroll
    for (int k = 0; k < 32; k++) n = fmaf(P[k], P[k], n);
    const float inv = 1.0f / (sqrtf(n) + EPSN);

    float4* tp = reinterpret_cast<float4*>(g_T + ((size_t)bh * NC + c) * 32);
#pragma unroll
    for (int q = 0; q < 8; q++)
        tp[q] = make_float4(P[4*q]*inv, P[4*q+1]*inv, P[4*q+2]*inv, P[4*q+3]*inv);
}

// ======================================================================
// Kernel 2a: segment-local exclusive scan. warp per (bh, seg); 64 T's.
// El_0 = id; El_{j+1} = N(T_j o El_j). Also stores segment total.
// ======================================================================
__global__ void k_scan1()
{
    const int lane = threadIdx.x & 31;
    const int gw   = blockIdx.x * (blockDim.x >> 5) + (threadIdx.x >> 5);  // [0, NCHAIN*NSEG)
    const int seg  = gw & (NSEG - 1);
    const int bh   = gw >> 2;

    float sg[32];
#pragma unroll
    for (int i = 0; i < 32; i++) sg[i] = csign(i, i ^ lane);

    const int c0 = seg * SEG;
    float Ev = (lane == 0) ? 1.0f : 0.0f;
    g_El[((size_t)bh * NC + c0) * 32 + lane] = Ev;

    for (int j = 0; j < SEG; j++){
        const float Tv = g_T[((size_t)bh * NC + c0 + j) * 32 + lane];
        float acc = 0.0f;
#pragma unroll
        for (int i = 0; i < 32; i++){
            const float Ti = __shfl_sync(0xffffffffu, Tv, i);
            const float Pi = __shfl_xor_sync(0xffffffffu, Ev, i);
            acc = fmaf(sg[i] * Ti, Pi, acc);
        }
        float ss = acc * acc;
#pragma unroll
        for (int off = 16; off; off >>= 1) ss += __shfl_xor_sync(0xffffffffu, ss, off);
        Ev = acc / (sqrtf(ss) + EPSN);
        if (j < SEG - 1)
            g_El[((size_t)bh * NC + c0 + j + 1) * 32 + lane] = Ev;
        else
            g_St[((size_t)bh * NSEG + seg) * 32 + lane] = Ev;   // inclusive seg total
    }
}

// ======================================================================
// Kernel 2b: segment exclusive prefixes. warp per bh; 3 serial GPs.
// ======================================================================
__global__ void k_scan2()
{
    const int lane = threadIdx.x & 31;
    const int bh   = blockIdx.x * (blockDim.x >> 5) + (threadIdx.x >> 5);

    float sg[32];
#pragma unroll
    for (int i = 0; i < 32; i++) sg[i] = csign(i, i ^ lane);

    float Gv = (lane == 0) ? 1.0f : 0.0f;
    g_G[((size_t)bh * NSEG + 0) * 32 + lane] = Gv;

#pragma unroll
    for (int j = 0; j < NSEG - 1; j++){
        const float Sv = g_St[((size_t)bh * NSEG + j) * 32 + lane];
        float acc = 0.0f;
#pragma unroll
        for (int i = 0; i < 32; i++){
            const float Si = __shfl_sync(0xffffffffu, Sv, i);
            const float Pi = __shfl_xor_sync(0xffffffffu, Gv, i);
            acc = fmaf(sg[i] * Si, Pi, acc);
        }
        float ss = acc * acc;
#pragma unroll
        for (int off = 16; off; off >>= 1) ss += __shfl_xor_sync(0xffffffffu, ss, off);
        Gv = acc / (sqrtf(ss) + EPSN);
        g_G[((size_t)bh * NSEG + j + 1) * 32 + lane] = Gv;
    }
}

// ======================================================================
// Kernel 3: seeds. thread per (bh, c): E = N(El o G).  Fully parallel.
// ======================================================================
__global__ void __launch_bounds__(128) k_seed()
{
    const int idx = blockIdx.x * blockDim.x + threadIdx.x;   // [0, NCHAIN*NC)
    const int c  = idx & (NC - 1);
    const int bh = idx >> 8;
    const int seg = c >> 6;                                  // SEG = 64

    float G[32];
    const float4* gp = reinterpret_cast<const float4*>(g_G + ((size_t)bh * NSEG + seg) * 32);
#pragma unroll
    for (int q = 0; q < 8; q++){
        const float4 v = __ldg(gp + q);
        G[4*q]=v.x; G[4*q+1]=v.y; G[4*q+2]=v.z; G[4*q+3]=v.w;
    }

    const float4* ep = reinterpret_cast<const float4*>(g_El + ((size_t)bh * NC + c) * 32);
    float Q[32];
    gp_f4(ep, G, Q);                                         // El left, G right

    float n = 0.f;
#pragma unroll
    for (int k = 0; k < 32; k++) n = fmaf(Q[k], Q[k], n);
    const float inv = 1.0f / (sqrtf(n) + EPSN);

    float4* op = reinterpret_cast<float4*>(g_E + ((size_t)bh * NC + c) * 32);
#pragma unroll
    for (int q = 0; q < 8; q++)
        op[q] = make_float4(Q[4*q]*inv, Q[4*q+1]*inv, Q[4*q+2]*inv, Q[4*q+3]*inv);
}

// ======================================================================
// Kernel 4: psi. thread per (bh, t): psi = N(L o E). Fully parallel.
// Stores transposed: psi_T[h*32+k][b*SS + t].
// ======================================================================
__global__ void __launch_bounds__(256) k_psi()
{
    const int idx = blockIdx.x * blockDim.x + threadIdx.x;   // [0, NCHAIN*SS)
    const int t  = idx & (SS - 1);
    const int bh = idx >> 11;
    const int b  = bh >> 3;
    const int h  = bh & 7;
    const int c  = t >> 3;                                   // CS = 8

    float E[32];
    const float4* ep = reinterpret_cast<const float4*>(g_E + ((size_t)bh * NC + c) * 32);
#pragma unroll
    for (int q = 0; q < 8; q++){
        const float4 v = __ldg(ep + q);
        E[4*q]=v.x; E[4*q+1]=v.y; E[4*q+2]=v.z; E[4*q+3]=v.w;
    }

    const float4* lp = reinterpret_cast<const float4*>(g_L + ((size_t)bh * SS + t) * 32);
    float Q[32];
    gp_f4(lp, E, Q);                                         // L left, E right

    float n = 0.f;
#pragma unroll
    for (int k = 0; k < 32; k++) n = fmaf(Q[k], Q[k], n);
    const float inv = 1.0f / (sqrtf(n) + EPSN);

    float* op = psi_T + (size_t)(h*32) * NROW + (size_t)b * SS + t;
#pragma unroll
    for (int k = 0; k < 32; k++)
        op[(size_t)k * NROW] = Q[k] * inv;                   // lane-coalesced (t adjacent)
}

// ======================================================================
// Kernel 5: projection. warp handles 32 consecutive rows; coalesced column
// loads from psi_T; W_out in smem.
// ======================================================================
__global__ void __launch_bounds__(256) k_proj(const float* __restrict__ W_out,
                                              const float* __restrict__ b_out,
                                              float* __restrict__ out)
{
    __shared__ float Wsm[256 * 32];
    __shared__ float bsm[32];

    const int tid = threadIdx.x;
    for (int i = tid; i < 256 * 32 / 4; i += 256)
        reinterpret_cast<float4*>(Wsm)[i] = __ldg(reinterpret_cast<const float4*>(W_out) + i);
    if (tid < 8)
        reinterpret_cast<float4*>(bsm)[tid] = __ldg(reinterpret_cast<const float4*>(b_out) + tid);
    __syncthreads();

    const int lane = tid & 31;
    const int gw   = blockIdx.x * 8 + (tid >> 5);
    const size_t r = (size_t)gw * 32 + lane;                 // r = b*SS + t

    const float* ap = psi_T + r;

    float acc[32];
#pragma unroll
    for (int j = 0; j < 32; j++) acc[j] = 0.f;

#pragma unroll 8
    for (int j = 0; j < 256; j++){
        const float a = __ldg(ap + (size_t)j * NROW);        // coalesced
#pragma unroll
        for (int q = 0; q < 8; q++){
            const float4 w = *reinterpret_cast<const float4*>(&Wsm[j*32 + q*4]);
            acc[q*4+0] = fmaf(a, w.x, acc[q*4+0]);
            acc[q*4+1] = fmaf(a, w.y, acc[q*4+1]);
            acc[q*4+2] = fmaf(a, w.z, acc[q*4+2]);
            acc[q*4+3] = fmaf(a, w.w, acc[q*4+3]);
        }
    }

#pragma unroll
    for (int j = 0; j < 32; j++) acc[j] += bsm[j];

    float n = 0.f;
#pragma unroll
    for (int j = 0; j < 32; j++) n = fmaf(acc[j], acc[j], n);
    const float inv = 1.0f / (sqrtf(n) + EPSN);

    float4* op = reinterpret_cast<float4*>(out + r * 32);
#pragma unroll
    for (int q = 0; q < 8; q++)
        op[q] = make_float4(acc[4*q]*inv, acc[4*q+1]*inv, acc[4*q+2]*inv, acc[4*q+3]*inv);
}

// ======================================================================
extern "C" void kernel_launch(void* const* d_in, const int* in_sizes, int n_in,
                              void* d_out, int out_size)
{
    const float* x     = (const float*)d_in[0];
    const float* W_in  = (const float*)d_in[1];
    const float* b_in  = (const float*)d_in[2];
    const float* W_out = (const float*)d_in[3];
    const float* b_out = (const float*)d_in[4];
    float* out = (float*)d_out;

    k_delta <<<(BB * SS) / 8, 256>>>(x, W_in, b_in);   // 16384 warps
    k_chunkL<<<(NCHAIN * NC) / 128, 128>>>();          // 4096 warps, 7 serial GPs
    k_scan1 <<<(NCHAIN * NSEG) / 8, 256>>>();          // 2048 warps, 64 serial combines
    k_scan2 <<<NCHAIN / 8, 256>>>();                   // 512 warps, 3 serial combines
    k_seed  <<<(NCHAIN * NC) / 128, 128>>>();          // fully parallel
    k_psi   <<<(NCHAIN * SS) / 256, 256>>>();          // fully parallel, 32768 warps
    k_proj  <<<NROW / (32 * 8), 256>>>(W_out, b_out, out);
}

// round 7
// speedup vs baseline: 7.6187x; 6.8860x over previous
#include <cuda_runtime.h>
#include <cstdint>
#include <cstddef>

// ---------------- Problem constants ----------------
#define BB 64
#define SS 2048
#define DD 6
#define HH 8
#define NCHAIN (BB*HH)      // 512 chains
#define CS 8                // steps per chunk
#define NC (SS/CS)          // 256 chunks per chain
#define SEG 32              // chunks per scan segment
#define NSEG (NC/SEG)       // 8 segments
#define NROW (BB*SS)        // 131072 rows
#define EPSN 1e-8f

// ============ Cl(4,1) ~ M4(C) via gamma matrices (constexpr tables) ========
struct CMat { int re[4][4]; int im[4][4]; };

__host__ __device__ constexpr CMat cid(){ CMat m{}; for(int r=0;r<4;r++) m.re[r][r]=1; return m; }

__host__ __device__ constexpr CMat cmul(const CMat&A, const CMat&B){
    CMat R{};
    for(int r=0;r<4;r++)for(int c=0;c<4;c++){
        int re=0, im=0;
        for(int k=0;k<4;k++){
            re += A.re[r][k]*B.re[k][c] - A.im[r][k]*B.im[k][c];
            im += A.re[r][k]*B.im[k][c] + A.im[r][k]*B.re[k][c];
        }
        R.re[r][c]=re; R.im[r][c]=im;
    }
    return R;
}

// gamma_i: squares +1,+1,+1,+1,-1 ; mutually anticommuting
__host__ __device__ constexpr CMat gammaM(int i){
    CMat m{};
    if(i==0){ m.re[0][2]=1; m.re[1][3]=1; m.re[2][0]=1; m.re[3][1]=1; }          // sx x I
    else if(i==1){ m.im[0][2]=-1; m.im[1][3]=-1; m.im[2][0]=1; m.im[3][1]=1; }   // sy x I
    else if(i==2){ m.re[0][1]=1; m.re[1][0]=1; m.re[2][3]=-1; m.re[3][2]=-1; }   // sz x sx
    else if(i==3){ m.im[0][1]=-1; m.im[1][0]=1; m.im[2][3]=1; m.im[3][2]=-1; }   // sz x sy
    else { m.im[0][0]=1; m.im[1][1]=-1; m.im[2][2]=-1; m.im[3][3]=1; }           // i*(sz x sz)
    return m;
}

struct Tables { int col[32][4]; int pc[32][4]; int sq[32]; };
// col[A][r]: the single nonzero column of Gamma_A in row r
// pc[A][r] : phase code 0:+1  1:+i  2:-1  3:-i
// sq[A]    : Gamma_A^2 = sq * I  (+1 or -1)
__host__ __device__ constexpr Tables build(){
    Tables t{};
    for(int A=0;A<32;A++){
        CMat M = cid();
        for(int i=0;i<5;i++) if((A>>i)&1) M = cmul(M, gammaM(i));  // ascending order
        for(int r=0;r<4;r++){
            for(int c=0;c<4;c++){
                if(M.re[r][c]!=0){ t.col[A][r]=c; t.pc[A][r]=(M.re[r][c]>0)?0:2; }
                else if(M.im[r][c]!=0){ t.col[A][r]=c; t.pc[A][r]=(M.im[r][c]>0)?1:3; }
            }
        }
        CMat M2 = cmul(M,M);
        t.sq[A] = M2.re[0][0];
    }
    return t;
}
// __device__ so it is visible (and compile-time folded) in device code
__device__ constexpr Tables TB = build();

// matrix storage layout: float M[32]: M[r*4+c] = Re, M[16+r*4+c] = Im

// ---------------- Scratch (device globals; no allocation) ----------------
__device__ static float g_d [(size_t)NCHAIN * SS * 32];     // delta matrices
__device__ static float g_L [(size_t)NCHAIN * SS * 32];     // local prefix matrices (raw)
__device__ static float g_T [(size_t)NCHAIN * NC * 32];     // chunk total matrices (normalized)
__device__ static float g_El[(size_t)NCHAIN * NC * 32];     // segment-local exclusive prefixes
__device__ static float g_St[(size_t)NCHAIN * NSEG * 32];   // segment totals
__device__ static float g_G [(size_t)NCHAIN * NSEG * 32];   // segment exclusive prefixes
__device__ static float g_E [(size_t)NCHAIN * NC * 32];     // per-chunk seed matrices
__device__ static float psi_T[(size_t)256 * NROW];          // psi components, [j][b*SS+t]

// ---------------- complex 4x4 matmul, D streamed from gmem -----------------
// Q = D * P   (D = left/new operand)
__device__ __forceinline__ void cmm_g(const float* __restrict__ Dp,
                                      const float P[32], float Q[32])
{
#pragma unroll
    for(int r=0;r<4;r++){
        const float4 drv = __ldg(reinterpret_cast<const float4*>(Dp) + r);      // re row
        const float4 div = __ldg(reinterpret_cast<const float4*>(Dp) + 4 + r);  // im row
        const float dr[4] = {drv.x, drv.y, drv.z, drv.w};
        const float di[4] = {div.x, div.y, div.z, div.w};
#pragma unroll
        for(int c=0;c<4;c++){
            float qre = 0.f, qim = 0.f;
#pragma unroll
            for(int k=0;k<4;k++){
                qre = fmaf( dr[k], P[k*4+c],    qre);
                qre = fmaf(-di[k], P[16+k*4+c], qre);
                qim = fmaf( dr[k], P[16+k*4+c], qim);
                qim = fmaf( di[k], P[k*4+c],    qim);
            }
            Q[r*4+c]    = qre;
            Q[16+r*4+c] = qim;
        }
    }
}

__device__ __forceinline__ void load32(const float* __restrict__ p, float M[32]){
#pragma unroll
    for(int q=0;q<8;q++){
        const float4 v = __ldg(reinterpret_cast<const float4*>(p) + q);
        M[4*q]=v.x; M[4*q+1]=v.y; M[4*q+2]=v.z; M[4*q+3]=v.w;
    }
}
__device__ __forceinline__ void store32(float* __restrict__ p, const float M[32], float s){
#pragma unroll
    for(int q=0;q<8;q++)
        reinterpret_cast<float4*>(p)[q] =
            make_float4(M[4*q]*s, M[4*q+1]*s, M[4*q+2]*s, M[4*q+3]*s);
}
// 1/(||x|| + eps) with ||x||^2 = Frobenius^2 / 4
__device__ __forceinline__ float mnorm_inv(const float M[32]){
    float n = 0.f;
#pragma unroll
    for(int k=0;k<32;k++) n = fmaf(M[k], M[k], n);
    return 1.0f / (sqrtf(0.25f*n) + EPSN);
}

// ======================================================================
// Kernel 0: delta -> matrix form. thread per (b,s,h).
// ======================================================================
__global__ void __launch_bounds__(256) k_delta(const float* __restrict__ x,
                                               const float* __restrict__ W_in,
                                               const float* __restrict__ b_in)
{
    __shared__ float Wt[DD*256];   // [d][k*8+h]
    __shared__ float bt[256];      // [k*8+h]

    const int tid = threadIdx.x;
    for (int i = tid; i < DD*256; i += 256){
        const int d = i >> 8, rem = i & 255, k = rem >> 3, h = rem & 7;
        Wt[i] = __ldg(W_in + d*256 + h*32 + k);
    }
    for (int i = tid; i < 256; i += 256){
        const int k = i >> 3, h = i & 7;
        bt[i] = __ldg(b_in + h*32 + k);
    }
    __syncthreads();

    const int bs = blockIdx.x * 32 + (tid >> 3);   // [0, B*S)
    const int h  = tid & 7;
    const int b  = bs >> 11;
    const int s  = bs & (SS - 1);

    const float* xp = x + (size_t)bs * DD;
    float xv[DD];
#pragma unroll
    for (int d = 0; d < DD; d++) xv[d] = __ldg(xp + d);

    float M[32];
#pragma unroll
    for (int k = 0; k < 32; k++) M[k] = 0.f;
    float n = 0.f;

#pragma unroll
    for (int A = 0; A < 32; A++){
        float u = bt[A*8 + h];
#pragma unroll
        for (int d = 0; d < DD; d++)
            u = fmaf(xv[d], Wt[d*256 + A*8 + h], u);
        if (A == 0) u += 1.0f;
        n = fmaf(u, u, n);
        // scatter x_A * Gamma_A into M
#pragma unroll
        for (int r = 0; r < 4; r++){
            const int c = TB.col[A][r];
            const int p = TB.pc[A][r];
            if      (p == 0) M[r*4+c]    += u;
            else if (p == 2) M[r*4+c]    -= u;
            else if (p == 1) M[16+r*4+c] += u;
            else             M[16+r*4+c] -= u;
        }
    }

    const float inv = 1.0f / (sqrtf(n) + EPSN);
    const int bh = b * HH + h;
    store32(g_d + ((size_t)bh * SS + s) * 32, M, inv);
}

// ======================================================================
// Kernel 1: chunk local prefixes. thread per (bh,c): 7 serial matmuls.
// ======================================================================
__global__ void __launch_bounds__(128) k_chunkL()
{
    const int idx = blockIdx.x * blockDim.x + threadIdx.x;   // [0, NCHAIN*NC)
    const int c  = idx & (NC - 1);
    const int bh = idx >> 8;

    const float* dbase = g_d + ((size_t)bh * SS + c * CS) * 32;
    float*       lbase = g_L + ((size_t)bh * SS + c * CS) * 32;

    float P[32], Q[32];
    load32(dbase, P);
    store32(lbase, P, 1.0f);

    for (int s = 1; s < CS; s++){
        cmm_g(dbase + s*32, P, Q);
        store32(lbase + s*32, Q, 1.0f);
#pragma unroll
        for (int k = 0; k < 32; k++) P[k] = Q[k];
    }

    const float inv = mnorm_inv(P);
    store32(g_T + ((size_t)bh * NC + c) * 32, P, inv);
}

// ======================================================================
// Kernel 2a: segment-local exclusive scan. thread per (bh,seg); 32 steps.
// ======================================================================
__global__ void __launch_bounds__(128) k_scan1()
{
    const int idx = blockIdx.x * blockDim.x + threadIdx.x;   // [0, NCHAIN*NSEG)
    const int seg = idx & (NSEG - 1);
    const int bh  = idx >> 3;
    const int c0  = seg * SEG;

    float E[32], Q[32];
#pragma unroll
    for (int k = 0; k < 32; k++) E[k] = 0.f;
#pragma unroll
    for (int r = 0; r < 4; r++) E[r*4+r] = 1.f;              // identity

    store32(g_El + ((size_t)bh * NC + c0) * 32, E, 1.0f);

    for (int j = 0; j < SEG; j++){
        cmm_g(g_T + ((size_t)bh * NC + c0 + j) * 32, E, Q);
        const float inv = mnorm_inv(Q);
#pragma unroll
        for (int k = 0; k < 32; k++) E[k] = Q[k] * inv;
        if (j < SEG - 1)
            store32(g_El + ((size_t)bh * NC + c0 + j + 1) * 32, E, 1.0f);
        else
            store32(g_St + ((size_t)bh * NSEG + seg) * 32, E, 1.0f);
    }
}

// ======================================================================
// Kernel 2b: segment exclusive prefixes. thread per bh; 7 steps.
// ======================================================================
__global__ void __launch_bounds__(128) k_scan2()
{
    const int bh = blockIdx.x * blockDim.x + threadIdx.x;    // [0, NCHAIN)

    float G[32], Q[32];
#pragma unroll
    for (int k = 0; k < 32; k++) G[k] = 0.f;
#pragma unroll
    for (int r = 0; r < 4; r++) G[r*4+r] = 1.f;

    store32(g_G + ((size_t)bh * NSEG + 0) * 32, G, 1.0f);

    for (int j = 0; j < NSEG - 1; j++){
        cmm_g(g_St + ((size_t)bh * NSEG + j) * 32, G, Q);
        const float inv = mnorm_inv(Q);
#pragma unroll
        for (int k = 0; k < 32; k++) G[k] = Q[k] * inv;
        store32(g_G + ((size_t)bh * NSEG + j + 1) * 32, G, 1.0f);
    }
}

// ======================================================================
// Kernel 3: seeds. thread per (bh,c): E = N(El * G). Fully parallel.
// ======================================================================
__global__ void __launch_bounds__(128) k_seed()
{
    const int idx = blockIdx.x * blockDim.x + threadIdx.x;   // [0, NCHAIN*NC)
    const int c  = idx & (NC - 1);
    const int bh = idx >> 8;
    const int seg = c / SEG;

    float G[32], Q[32];
    load32(g_G + ((size_t)bh * NSEG + seg) * 32, G);
    cmm_g(g_El + ((size_t)bh * NC + c) * 32, G, Q);          // El left, G right

    const float inv = mnorm_inv(Q);
    store32(g_E + ((size_t)bh * NC + c) * 32, Q, inv);
}

// ======================================================================
// Kernel 4: psi. thread per (bh,t): M = L*E; convert back; normalize; store.
// ======================================================================
__global__ void __launch_bounds__(256) k_psi()
{
    const int idx = blockIdx.x * blockDim.x + threadIdx.x;   // [0, NCHAIN*SS)
    const int t  = idx & (SS - 1);
    const int bh = idx >> 11;
    const int b  = bh >> 3;
    const int h  = bh & 7;
    const int c  = t >> 3;                                   // CS = 8

    float E[32], Q[32];
    load32(g_E + ((size_t)bh * NC + c) * 32, E);
    cmm_g(g_L + ((size_t)bh * SS + t) * 32, E, Q);           // L left, E right

    // inverse transform: t_A = sq_A * sum_r Re(phase_{A,r} * M[col[A][r]][r])
    float tc[32];
    float n = 0.f;
#pragma unroll
    for (int A = 0; A < 32; A++){
        float v = 0.f;
#pragma unroll
        for (int r = 0; r < 4; r++){
            const int rr = TB.col[A][r];
            const int p  = TB.pc[A][r];
            const float e = (p==0 || p==2) ? Q[rr*4+r] : Q[16+rr*4+r];
            const int pos = ((p==0 || p==3) ? 1 : -1) * TB.sq[A];
            v = (pos > 0) ? (v + e) : (v - e);
        }
        tc[A] = v;
        n = fmaf(v, v, n);
    }
    const float inv = 1.0f / (sqrtf(n) + 4.0f*EPSN);

    float* op = psi_T + (size_t)(h*32) * NROW + (size_t)b * SS + t;
#pragma unroll
    for (int k = 0; k < 32; k++)
        op[(size_t)k * NROW] = tc[k] * inv;                  // lane-coalesced
}

// ======================================================================
// Kernel 5: projection (unchanged from R5).
// ======================================================================
__global__ void __launch_bounds__(256) k_proj(const float* __restrict__ W_out,
                                              const float* __restrict__ b_out,
                                              float* __restrict__ out)
{
    __shared__ float Wsm[256 * 32];
    __shared__ float bsm[32];

    const int tid = threadIdx.x;
    for (int i = tid; i < 256 * 32 / 4; i += 256)
        reinterpret_cast<float4*>(Wsm)[i] = __ldg(reinterpret_cast<const float4*>(W_out) + i);
    if (tid < 8)
        reinterpret_cast<float4*>(bsm)[tid] = __ldg(reinterpret_cast<const float4*>(b_out) + tid);
    __syncthreads();

    const int lane = tid & 31;
    const int gw   = blockIdx.x * 8 + (tid >> 5);
    const size_t r = (size_t)gw * 32 + lane;                 // r = b*SS + t

    const float* ap = psi_T + r;

    float acc[32];
#pragma unroll
    for (int j = 0; j < 32; j++) acc[j] = 0.f;

#pragma unroll 8
    for (int j = 0; j < 256; j++){
        const float a = __ldg(ap + (size_t)j * NROW);
#pragma unroll
        for (int q = 0; q < 8; q++){
            const float4 w = *reinterpret_cast<const float4*>(&Wsm[j*32 + q*4]);
            acc[q*4+0] = fmaf(a, w.x, acc[q*4+0]);
            acc[q*4+1] = fmaf(a, w.y, acc[q*4+1]);
            acc[q*4+2] = fmaf(a, w.z, acc[q*4+2]);
            acc[q*4+3] = fmaf(a, w.w, acc[q*4+3]);
        }
    }

#pragma unroll
    for (int j = 0; j < 32; j++) acc[j] += bsm[j];

    float n = 0.f;
#pragma unroll
    for (int j = 0; j < 32; j++) n = fmaf(acc[j], acc[j], n);
    const float inv = 1.0f / (sqrtf(n) + EPSN);

    float4* op = reinterpret_cast<float4*>(out + r * 32);
#pragma unroll
    for (int q = 0; q < 8; q++)
        op[q] = make_float4(acc[4*q]*inv, acc[4*q+1]*inv, acc[4*q+2]*inv, acc[4*q+3]*inv);
}

// ======================================================================
extern "C" void kernel_launch(void* const* d_in, const int* in_sizes, int n_in,
                              void* d_out, int out_size)
{
    const float* x     = (const float*)d_in[0];
    const float* W_in  = (const float*)d_in[1];
    const float* b_in  = (const float*)d_in[2];
    const float* W_out = (const float*)d_in[3];
    const float* b_out = (const float*)d_in[4];
    float* out = (float*)d_out;

    k_delta <<<(BB*SS*HH)/256, 256>>>(x, W_in, b_in);   // 4096 blocks
    k_chunkL<<<(NCHAIN*NC)/128, 128>>>();               // 1024 blocks
    k_scan1 <<<(NCHAIN*NSEG)/128, 128>>>();             // 32 blocks
    k_scan2 <<<NCHAIN/128, 128>>>();                    // 4 blocks
    k_seed  <<<(NCHAIN*NC)/128, 128>>>();               // 1024 blocks
    k_psi   <<<(NCHAIN*SS)/256, 256>>>();               // 4096 blocks
    k_proj  <<<NROW/(32*8), 256>>>(W_out, b_out, out);  // 512 blocks
}